// round 1
// baseline (speedup 1.0000x reference)
#include <cuda_runtime.h>

// Problem dims (fixed per setup_inputs)
#define MB 8192   // batch rows (M)
#define KD 1024   // inner dim (K)
#define ND 4096   // out features (N)

// Scratch for fused epilogue terms (no device allocs allowed -> __device__ globals)
__device__ float g_xsq[MB];
__device__ float g_wsq[ND];

// ---------------------------------------------------------------------------
// ||x_b||^2 : one warp per row, float4 loads, warp shuffle reduce.
// grid = MB/8 blocks of 256 threads (8 warps -> 8 rows per block)
// ---------------------------------------------------------------------------
__global__ void xsq_kernel(const float* __restrict__ x) {
    int row  = blockIdx.x * 8 + (threadIdx.x >> 5);
    int lane = threadIdx.x & 31;
    const float4* xr = reinterpret_cast<const float4*>(x + (size_t)row * KD);
    float s = 0.f;
    #pragma unroll 4
    for (int i = lane; i < KD / 4; i += 32) {
        float4 v = xr[i];
        s += v.x * v.x + v.y * v.y + v.z * v.z + v.w * v.w;
    }
    #pragma unroll
    for (int o = 16; o > 0; o >>= 1) s += __shfl_xor_sync(0xffffffffu, s, o);
    if (lane == 0) g_xsq[row] = s;
}

// ---------------------------------------------------------------------------
// ||w_:,o||^2 : W is [K, N] row-major, so a column is strided by N.
// Each block handles 64 columns; 4 K-partitions per column (coalesced rows),
// reduced through shared memory. grid = ND/64 = 64 blocks, 256 threads.
// ---------------------------------------------------------------------------
__global__ void wsq_kernel(const float* __restrict__ w) {
    __shared__ float red[4][64];
    int colBase = blockIdx.x * 64;
    int c    = threadIdx.x & 63;   // column within group
    int part = threadIdx.x >> 6;   // 0..3 K-partition
    float s = 0.f;
    int k0 = part * (KD / 4);
    #pragma unroll 4
    for (int k = k0; k < k0 + KD / 4; ++k) {
        float v = w[(size_t)k * ND + colBase + c];
        s += v * v;
    }
    red[part][c] = s;
    __syncthreads();
    if (part == 0)
        g_wsq[colBase + c] = red[0][c] + red[1][c] + red[2][c] + red[3][c];
}

// ---------------------------------------------------------------------------
// Fused GEMM + epilogue:
//   C[b,o] = g_xsq[b] + g_wsq[o] - 2 * sum_k A[b,k]*W[k,o]
// Classic 128x128 block tile, BK=8, 8x8 per-thread micro-tile, 256 threads.
// A = x [M,K] row-major; Bw = W [K,N] row-major; C [M,N] row-major.
// ---------------------------------------------------------------------------
__global__ __launch_bounds__(256, 2)
void rbf_gemm_kernel(const float* __restrict__ A,
                     const float* __restrict__ Bw,
                     float* __restrict__ C) {
    __shared__ float As[8][128];   // A tile transposed: As[k][m]
    __shared__ float Bs[8][128];   // B tile:            Bs[k][n]

    const int tid     = threadIdx.x;
    const int rowBase = blockIdx.y * 128;
    const int colBase = blockIdx.x * 128;

    const float* Aptr = A  + (size_t)rowBase * KD;
    const float* Bptr = Bw + colBase;

    // Global-load assignments (one float4 each per tile per buffer)
    const int aRow = tid >> 1;          // 0..127
    const int aCol = (tid & 1) * 4;     // 0 or 4
    const int bRow = tid >> 5;          // 0..7
    const int bCol = (tid & 31) * 4;    // 0..124

    // Compute assignment: 16x16 thread grid of 8x8 micro-tiles
    const int tr = (tid >> 4) * 8;      // row offset in tile
    const int tc = (tid & 15) * 8;      // col offset in tile

    float acc[8][8];
    #pragma unroll
    for (int i = 0; i < 8; ++i)
        #pragma unroll
        for (int j = 0; j < 8; ++j) acc[i][j] = 0.f;

    float regM[8], regN[8];

    for (int k0 = 0; k0 < KD; k0 += 8) {
        float4 a4 = *reinterpret_cast<const float4*>(
            Aptr + (size_t)aRow * KD + k0 + aCol);
        float4 b4 = *reinterpret_cast<const float4*>(
            Bptr + (size_t)(k0 + bRow) * ND + bCol);

        As[aCol + 0][aRow] = a4.x;
        As[aCol + 1][aRow] = a4.y;
        As[aCol + 2][aRow] = a4.z;
        As[aCol + 3][aRow] = a4.w;
        *reinterpret_cast<float4*>(&Bs[bRow][bCol]) = b4;
        __syncthreads();

        #pragma unroll
        for (int k = 0; k < 8; ++k) {
            #pragma unroll
            for (int i = 0; i < 8; ++i) regM[i] = As[k][tr + i];
            #pragma unroll
            for (int j = 0; j < 8; ++j) regN[j] = Bs[k][tc + j];
            #pragma unroll
            for (int i = 0; i < 8; ++i)
                #pragma unroll
                for (int j = 0; j < 8; ++j)
                    acc[i][j] += regM[i] * regN[j];
        }
        __syncthreads();
    }

    // Epilogue: out = xsq + wsq - 2*cross, vectorized float4 stores
    float wsq[8];
    #pragma unroll
    for (int j = 0; j < 8; ++j) wsq[j] = g_wsq[colBase + tc + j];

    #pragma unroll
    for (int i = 0; i < 8; ++i) {
        const float xs = g_xsq[rowBase + tr + i];
        float* crow = C + (size_t)(rowBase + tr + i) * ND + colBase + tc;
        #pragma unroll
        for (int j = 0; j < 8; j += 4) {
            float4 o;
            o.x = xs + wsq[j + 0] - 2.f * acc[i][j + 0];
            o.y = xs + wsq[j + 1] - 2.f * acc[i][j + 1];
            o.z = xs + wsq[j + 2] - 2.f * acc[i][j + 2];
            o.w = xs + wsq[j + 3] - 2.f * acc[i][j + 3];
            *reinterpret_cast<float4*>(crow + j) = o;
        }
    }
}

// ---------------------------------------------------------------------------
// kernel_launch: x = d_in[0] (8192x1024 f32), weight = d_in[1] (1024x4096 f32)
// out = d_out (8192x4096 f32). Three graph-capturable launches, no allocs.
// ---------------------------------------------------------------------------
extern "C" void kernel_launch(void* const* d_in, const int* in_sizes, int n_in,
                              void* d_out, int out_size) {
    const float* x = (const float*)d_in[0];
    const float* w = (const float*)d_in[1];
    float* out = (float*)d_out;

    xsq_kernel<<<MB / 8, 256>>>(x);
    wsq_kernel<<<ND / 64, 256>>>(w);

    dim3 grid(ND / 128, MB / 128);  // (32, 64)
    rbf_gemm_kernel<<<grid, 256>>>(x, w, out);
}

// round 7
// speedup vs baseline: 7.1194x; 7.1194x over previous
#include <cuda_runtime.h>
#include <cuda_bf16.h>
#include <cstdint>

#define MB 8192   // M
#define KD 1024   // K
#define ND 4096   // N

// ---------------- device scratch (no allocs allowed) ----------------
__device__ float g_xsq[MB];
__device__ float g_wsq[ND];
__device__ __nv_bfloat16 g_xb[(size_t)MB * KD];   // x in bf16, [M][K]
__device__ __nv_bfloat16 g_wb[(size_t)ND * KD];   // W in bf16, TRANSPOSED [N][K]

// ---------------- helpers ----------------
__device__ __forceinline__ uint32_t smem_u32(const void* p) {
    uint32_t a;
    asm("{ .reg .u64 t; cvta.to.shared.u64 t, %1; cvt.u32.u64 %0, t; }"
        : "=r"(a) : "l"(p));
    return a;
}

__device__ __forceinline__ void cp_async16(uint32_t dst, const void* src) {
    asm volatile("cp.async.cg.shared.global [%0], [%1], 16;"
                 :: "r"(dst), "l"(src) : "memory");
}

__device__ __forceinline__ uint32_t swz(uint32_t b) {  // SW128: Swizzle<3,4,3>
    return b ^ ((b >> 3) & 0x70);
}

__device__ __forceinline__ void ldsm_x4(uint32_t* r, uint32_t addr) {
    asm volatile("ldmatrix.sync.aligned.m8n8.x4.shared.b16 {%0,%1,%2,%3}, [%4];"
                 : "=r"(r[0]), "=r"(r[1]), "=r"(r[2]), "=r"(r[3]) : "r"(addr));
}

__device__ __forceinline__ void mma16816(float* d, const uint32_t* a,
                                         uint32_t b0, uint32_t b1) {
    asm volatile(
        "mma.sync.aligned.m16n8k16.row.col.f32.bf16.bf16.f32 "
        "{%0,%1,%2,%3}, {%4,%5,%6,%7}, {%8,%9}, {%0,%1,%2,%3};"
        : "+f"(d[0]), "+f"(d[1]), "+f"(d[2]), "+f"(d[3])
        : "r"(a[0]), "r"(a[1]), "r"(a[2]), "r"(a[3]), "r"(b0), "r"(b1));
}

// ---------------------------------------------------------------------------
// convert x -> bf16 and compute ||x_b||^2 (one warp per row)
// ---------------------------------------------------------------------------
__global__ void convert_x_kernel(const float* __restrict__ x) {
    int row  = blockIdx.x * 8 + (threadIdx.x >> 5);
    int lane = threadIdx.x & 31;
    const float4* xr = reinterpret_cast<const float4*>(x + (size_t)row * KD);
    uint2* dst = reinterpret_cast<uint2*>(g_xb + (size_t)row * KD);
    float s = 0.f;
    #pragma unroll 4
    for (int i = lane; i < KD / 4; i += 32) {
        float4 v = xr[i];
        s += v.x * v.x + v.y * v.y + v.z * v.z + v.w * v.w;
        __nv_bfloat162 lo = __floats2bfloat162_rn(v.x, v.y);
        __nv_bfloat162 hi = __floats2bfloat162_rn(v.z, v.w);
        uint2 u;
        u.x = *reinterpret_cast<uint32_t*>(&lo);
        u.y = *reinterpret_cast<uint32_t*>(&hi);
        dst[i] = u;
    }
    #pragma unroll
    for (int o = 16; o > 0; o >>= 1) s += __shfl_xor_sync(0xffffffffu, s, o);
    if (lane == 0) g_xsq[row] = s;
}

// ---------------------------------------------------------------------------
// convert W [K][N] -> bf16 transposed g_wb [N][K], via SMEM 64x32 tile
// ---------------------------------------------------------------------------
__global__ void convert_w_kernel(const float* __restrict__ w) {
    __shared__ __nv_bfloat16 t[64][34];
    int k0 = blockIdx.x * 64;
    int n0 = blockIdx.y * 32;
    int tid = threadIdx.x;
    int c = tid & 31, r0 = tid >> 5;
    #pragma unroll
    for (int p = 0; p < 8; ++p) {
        int r = p * 8 + r0;
        t[r][c] = __float2bfloat16_rn(w[(size_t)(k0 + r) * ND + n0 + c]);
    }
    __syncthreads();
    int n = tid >> 3, seg = (tid & 7) * 8;
    __nv_bfloat16 tmp[8];
    #pragma unroll
    for (int i = 0; i < 8; ++i) tmp[i] = t[seg + i][n];
    *reinterpret_cast<uint4*>(g_wb + (size_t)(n0 + n) * KD + k0 + seg) =
        *reinterpret_cast<uint4*>(tmp);
}

// ---------------------------------------------------------------------------
// ||w_:,o||^2 in fp32 from original W (exact)
// ---------------------------------------------------------------------------
__global__ void wsq_kernel(const float* __restrict__ w) {
    __shared__ float red[4][64];
    int colBase = blockIdx.x * 64;
    int c = threadIdx.x & 63;
    int part = threadIdx.x >> 6;
    float s = 0.f;
    int k0 = part * (KD / 4);
    #pragma unroll 4
    for (int k = k0; k < k0 + KD / 4; ++k) {
        float v = w[(size_t)k * ND + colBase + c];
        s += v * v;
    }
    red[part][c] = s;
    __syncthreads();
    if (part == 0)
        g_wsq[colBase + c] = red[0][c] + red[1][c] + red[2][c] + red[3][c];
}

// ---------------------------------------------------------------------------
// mma.sync bf16 GEMM + fused epilogue:
//   C[m,n] = xsq[m] + wsq[n] - 2 * (x @ W)[m,n]
// 128x128 CTA tile, K-chunks of 64 (128B SW128 rows), double-buffered cp.async
// 8 warps, 64x32 warp tile, m16n8k16 HMMA, f32 accum.
// ---------------------------------------------------------------------------
#define KC 64
#define NCHUNK (KD / KC)
#define SMEM_BYTES (4 * 16384)   // A0,A1,B0,B1

__global__ __launch_bounds__(256, 2)
void rbf_mma_gemm(float* __restrict__ C) {
    extern __shared__ __align__(1024) char smem[];
    const uint32_t sb = smem_u32(smem);
    const uint32_t A0 = sb, A1 = sb + 16384, B0 = sb + 32768, B1 = sb + 49152;

    const int tid  = threadIdx.x;
    const int lane = tid & 31;
    const int wid  = tid >> 5;
    const int wm   = (wid & 1) * 64;    // warp M offset (2 warps in M)
    const int wn   = (wid >> 1) * 32;   // warp N offset (4 warps in N)
    const int rowBase = blockIdx.y * 128;
    const int colBase = blockIdx.x * 128;

    // cp.async geometry: 256 threads x 4 iters x 16B per tile
    const int lr  = tid >> 3;          // 0..31
    const int seg = (tid & 7) * 16;    // byte 0..112

    auto load_chunk = [&](int c, int buf) {
        const uint32_t aT = buf ? A1 : A0;
        const uint32_t bT = buf ? B1 : B0;
        const size_t k0 = (size_t)c * KC;
        #pragma unroll
        for (int p = 0; p < 4; ++p) {
            int r = p * 32 + lr;
            cp_async16(aT + swz(r * 128 + seg),
                       (const char*)(g_xb + (size_t)(rowBase + r) * KD + k0) + seg);
            cp_async16(bT + swz(r * 128 + seg),
                       (const char*)(g_wb + (size_t)(colBase + r) * KD + k0) + seg);
        }
        asm volatile("cp.async.commit_group;" ::: "memory");
    };

    // ldmatrix lane geometry: lanes 0-15 -> rows, lanes 16-31 -> +16B col
    const int rl = lane & 15;
    const int hi = (lane >> 4) * 16;

    float acc[4][4][4];   // [m16 tile][n8 frag][reg]
    #pragma unroll
    for (int i = 0; i < 4; ++i)
        #pragma unroll
        for (int j = 0; j < 4; ++j)
            #pragma unroll
            for (int k = 0; k < 4; ++k) acc[i][j][k] = 0.f;

    load_chunk(0, 0);
    for (int c = 0; c < NCHUNK; ++c) {
        if (c + 1 < NCHUNK) {
            load_chunk(c + 1, (c + 1) & 1);
            asm volatile("cp.async.wait_group 1;" ::: "memory");
        } else {
            asm volatile("cp.async.wait_group 0;" ::: "memory");
        }
        __syncthreads();

        const uint32_t aT = (c & 1) ? A1 : A0;
        const uint32_t bT = (c & 1) ? B1 : B0;

        #pragma unroll
        for (int ks = 0; ks < 4; ++ks) {
            uint32_t a[4][4], bq[2][4];
            #pragma unroll
            for (int mt = 0; mt < 4; ++mt)
                ldsm_x4(a[mt], aT + swz((wm + mt * 16 + rl) * 128 + ks * 32 + hi));
            #pragma unroll
            for (int nt = 0; nt < 2; ++nt)
                ldsm_x4(bq[nt], bT + swz((wn + nt * 16 + rl) * 128 + ks * 32 + hi));
            #pragma unroll
            for (int mt = 0; mt < 4; ++mt) {
                #pragma unroll
                for (int nt = 0; nt < 2; ++nt) {
                    // x4 on B^T[N][K]: r0=(n0-7,k0-7) r1=(n8-15,k0-7)
                    //                  r2=(n0-7,k8-15) r3=(n8-15,k8-15)
                    mma16816(acc[mt][nt * 2 + 0], a[mt], bq[nt][0], bq[nt][2]);
                    mma16816(acc[mt][nt * 2 + 1], a[mt], bq[nt][1], bq[nt][3]);
                }
            }
        }
        __syncthreads();   // protect buffer (c&1) before iter c+1 overwrites it
    }

    // Epilogue: lane l -> row g=l>>2 (+8), cols 2*(l&3) within each n8 frag
    const int g  = lane >> 2;
    const int tg = (lane & 3) * 2;
    #pragma unroll
    for (int mt = 0; mt < 4; ++mt) {
        const int r0 = rowBase + wm + mt * 16 + g;
        const float xs0 = g_xsq[r0];
        const float xs1 = g_xsq[r0 + 8];
        float* p0 = C + (size_t)r0 * ND + colBase + wn;
        float* p1 = p0 + (size_t)8 * ND;
        #pragma unroll
        for (int nf = 0; nf < 4; ++nf) {
            const int col = nf * 8 + tg;
            const float w0 = g_wsq[colBase + wn + col];
            const float w1 = g_wsq[colBase + wn + col + 1];
            float2 v0, v1;
            v0.x = xs0 + w0 - 2.f * acc[mt][nf][0];
            v0.y = xs0 + w1 - 2.f * acc[mt][nf][1];
            v1.x = xs1 + w0 - 2.f * acc[mt][nf][2];
            v1.y = xs1 + w1 - 2.f * acc[mt][nf][3];
            *reinterpret_cast<float2*>(p0 + col) = v0;
            *reinterpret_cast<float2*>(p1 + col) = v1;
        }
    }
}

// ---------------------------------------------------------------------------
extern "C" void kernel_launch(void* const* d_in, const int* in_sizes, int n_in,
                              void* d_out, int out_size) {
    const float* x = (const float*)d_in[0];
    const float* w = (const float*)d_in[1];
    float* out = (float*)d_out;

    convert_x_kernel<<<MB / 8, 256>>>(x);
    convert_w_kernel<<<dim3(KD / 64, ND / 32), 256>>>(w);
    wsq_kernel<<<ND / 64, 256>>>(w);

    cudaFuncSetAttribute(rbf_mma_gemm,
                         cudaFuncAttributeMaxDynamicSharedMemorySize, SMEM_BYTES);
    rbf_mma_gemm<<<dim3(ND / 128, MB / 128), 256, SMEM_BYTES>>>(out);
}

// round 8
// speedup vs baseline: 7.4087x; 1.0406x over previous
#include <cuda_runtime.h>
#include <cuda_bf16.h>
#include <cstdint>

#define MB 8192   // M
#define KD 1024   // K
#define ND 4096   // N

// ---------------- device scratch (no allocs allowed) ----------------
__device__ float g_xsq[MB];
__device__ float g_wsq[ND];
__device__ __nv_bfloat16 g_xb[(size_t)MB * KD];   // x in bf16, [M][K]
__device__ __nv_bfloat16 g_wb[(size_t)ND * KD];   // W in bf16, TRANSPOSED [N][K]

// ---------------- helpers ----------------
__device__ __forceinline__ uint32_t smem_u32(const void* p) {
    uint32_t a;
    asm("{ .reg .u64 t; cvta.to.shared.u64 t, %1; cvt.u32.u64 %0, t; }"
        : "=r"(a) : "l"(p));
    return a;
}

__device__ __forceinline__ void cp_async16(uint32_t dst, const void* src) {
    asm volatile("cp.async.cg.shared.global [%0], [%1], 16;"
                 :: "r"(dst), "l"(src) : "memory");
}

__device__ __forceinline__ uint32_t swz(uint32_t b) {  // SW128: Swizzle<3,4,3>
    return b ^ ((b >> 3) & 0x70);
}

__device__ __forceinline__ void ldsm_x4(uint32_t* r, uint32_t addr) {
    asm volatile("ldmatrix.sync.aligned.m8n8.x4.shared.b16 {%0,%1,%2,%3}, [%4];"
                 : "=r"(r[0]), "=r"(r[1]), "=r"(r[2]), "=r"(r[3]) : "r"(addr));
}

__device__ __forceinline__ void mma16816(float* d, const uint32_t* a,
                                         uint32_t b0, uint32_t b1) {
    asm volatile(
        "mma.sync.aligned.m16n8k16.row.col.f32.bf16.bf16.f32 "
        "{%0,%1,%2,%3}, {%4,%5,%6,%7}, {%8,%9}, {%0,%1,%2,%3};"
        : "+f"(d[0]), "+f"(d[1]), "+f"(d[2]), "+f"(d[3])
        : "r"(a[0]), "r"(a[1]), "r"(a[2]), "r"(a[3]), "r"(b0), "r"(b1));
}

// ---------------------------------------------------------------------------
// convert x -> bf16 and compute ||x_b||^2 (one warp per row)
// ---------------------------------------------------------------------------
__global__ void convert_x_kernel(const float* __restrict__ x) {
    int row  = blockIdx.x * 8 + (threadIdx.x >> 5);
    int lane = threadIdx.x & 31;
    const float4* xr = reinterpret_cast<const float4*>(x + (size_t)row * KD);
    uint2* dst = reinterpret_cast<uint2*>(g_xb + (size_t)row * KD);
    float s = 0.f;
    #pragma unroll 8
    for (int i = lane; i < KD / 4; i += 32) {
        float4 v = xr[i];
        s += v.x * v.x + v.y * v.y + v.z * v.z + v.w * v.w;
        __nv_bfloat162 lo = __floats2bfloat162_rn(v.x, v.y);
        __nv_bfloat162 hi = __floats2bfloat162_rn(v.z, v.w);
        uint2 u;
        u.x = *reinterpret_cast<uint32_t*>(&lo);
        u.y = *reinterpret_cast<uint32_t*>(&hi);
        dst[i] = u;
    }
    #pragma unroll
    for (int o = 16; o > 0; o >>= 1) s += __shfl_xor_sync(0xffffffffu, s, o);
    if (lane == 0) g_xsq[row] = s;
}

// ---------------------------------------------------------------------------
// Fused: convert W [K][N] -> bf16 transposed g_wb [N][K]  AND  g_wsq (fp32).
// One block owns a 32-column stripe over the full K. grid = ND/32, 256 thr.
// ---------------------------------------------------------------------------
__global__ void convert_w_fused(const float* __restrict__ w) {
    __shared__ __nv_bfloat16 t[64][34];
    __shared__ float red[8][32];
    const int n0  = blockIdx.x * 32;
    const int tid = threadIdx.x;
    const int c   = tid & 31, r0 = tid >> 5;
    const int n   = tid >> 3, seg = (tid & 7) * 8;

    float sq = 0.f;
    for (int k0 = 0; k0 < KD; k0 += 64) {
        #pragma unroll
        for (int p = 0; p < 8; ++p) {
            int r = p * 8 + r0;
            float v = w[(size_t)(k0 + r) * ND + n0 + c];
            sq += v * v;
            t[r][c] = __float2bfloat16_rn(v);
        }
        __syncthreads();
        __nv_bfloat16 tmp[8];
        #pragma unroll
        for (int i = 0; i < 8; ++i) tmp[i] = t[seg + i][n];
        *reinterpret_cast<uint4*>(g_wb + (size_t)(n0 + n) * KD + k0 + seg) =
            *reinterpret_cast<uint4*>(tmp);
        __syncthreads();
    }
    red[r0][c] = sq;
    __syncthreads();
    if (tid < 32) {
        float s = 0.f;
        #pragma unroll
        for (int p = 0; p < 8; ++p) s += red[p][tid];
        g_wsq[n0 + tid] = s;
    }
}

// ---------------------------------------------------------------------------
// mma.sync bf16 GEMM + fused epilogue:
//   C[m,n] = xsq[m] + wsq[n] - 2 * (x @ W)[m,n]
// 128x128 CTA tile, K-chunks of 64, 3-stage cp.async pipeline (one barrier
// per chunk), 8 warps, 64x32 warp tile, m16n8k16 HMMA f32 accum,
// XOR-based ldmatrix addressing (SW128 mask invariant in ks).
// ---------------------------------------------------------------------------
#define KC 64
#define NCH (KD / KC)        // 16
#define STGB 16384           // bytes per operand per stage
#define SMEM_BYTES (6 * STGB)  // 3 stages x (A + B) = 96 KB

__global__ __launch_bounds__(256, 2)
void rbf_mma_gemm(float* __restrict__ C) {
    extern __shared__ __align__(1024) char smem[];
    const uint32_t sb = smem_u32(smem);
    // stage s: A at sb + s*16K, B at sb + 48K + s*16K

    const int tid  = threadIdx.x;
    const int lane = tid & 31;
    const int wid  = tid >> 5;
    const int wm   = (wid & 1) * 64;    // warp M offset
    const int wn   = (wid >> 1) * 32;   // warp N offset
    const int rowBase = blockIdx.y * 128;
    const int colBase = blockIdx.x * 128;

    // cp.async geometry: 256 threads x 4 rows x 16B per operand tile
    const int lr  = tid >> 3;          // 0..31
    const int seg = (tid & 7) * 16;    // byte 0..112

    auto load_chunk = [&](int c, int s) {
        const uint32_t aT = sb + (uint32_t)s * STGB;
        const uint32_t bT = sb + 3 * STGB + (uint32_t)s * STGB;
        const size_t k0 = (size_t)c * KC;
        #pragma unroll
        for (int p = 0; p < 4; ++p) {
            int r = p * 32 + lr;
            cp_async16(aT + swz(r * 128 + seg),
                       (const char*)(g_xb + (size_t)(rowBase + r) * KD + k0) + seg);
            cp_async16(bT + swz(r * 128 + seg),
                       (const char*)(g_wb + (size_t)(colBase + r) * KD + k0) + seg);
        }
        asm volatile("cp.async.commit_group;" ::: "memory");
    };

    // ldmatrix base offsets (swizzled once; ks advances via XOR of ks*32,
    // valid because the SW128 mask depends only on bits 7-9 = row bits)
    const int rl = lane & 15;
    const int hi = (lane >> 4) * 16;
    uint32_t offA[4], offB[2];
    #pragma unroll
    for (int mt = 0; mt < 4; ++mt)
        offA[mt] = swz((uint32_t)(wm + mt * 16 + rl) * 128 + hi);
    #pragma unroll
    for (int nt = 0; nt < 2; ++nt)
        offB[nt] = swz((uint32_t)(wn + nt * 16 + rl) * 128 + hi);

    float acc[4][4][4];
    #pragma unroll
    for (int i = 0; i < 4; ++i)
        #pragma unroll
        for (int j = 0; j < 4; ++j)
            #pragma unroll
            for (int k = 0; k < 4; ++k) acc[i][j][k] = 0.f;

    load_chunk(0, 0);
    load_chunk(1, 1);

    int s = 0, s2 = 2;   // stage of chunk c, stage for chunk c+2
    for (int c = 0; c < NCH; ++c) {
        asm volatile("cp.async.wait_group 1;" ::: "memory");
        __syncthreads();   // also guarantees all warps done computing c-1

        const uint32_t aT = sb + (uint32_t)s * STGB;
        const uint32_t bT = sb + 3 * STGB + (uint32_t)s * STGB;

        #pragma unroll
        for (int ks = 0; ks < 4; ++ks) {
            uint32_t a[4][4], bq[2][4];
            #pragma unroll
            for (int mt = 0; mt < 4; ++mt)
                ldsm_x4(a[mt], aT + (offA[mt] ^ (ks << 5)));
            #pragma unroll
            for (int nt = 0; nt < 2; ++nt)
                ldsm_x4(bq[nt], bT + (offB[nt] ^ (ks << 5)));
            #pragma unroll
            for (int mt = 0; mt < 4; ++mt) {
                #pragma unroll
                for (int nt = 0; nt < 2; ++nt) {
                    mma16816(acc[mt][nt * 2 + 0], a[mt], bq[nt][0], bq[nt][2]);
                    mma16816(acc[mt][nt * 2 + 1], a[mt], bq[nt][1], bq[nt][3]);
                }
            }
        }

        if (c + 2 < NCH) load_chunk(c + 2, s2);
        s  = (s  == 2) ? 0 : s + 1;
        s2 = (s2 == 2) ? 0 : s2 + 1;
    }

    // Epilogue: lane l -> row g=l>>2 (+8), cols 2*(l&3) within each n8 frag
    const int g  = lane >> 2;
    const int tg = (lane & 3) * 2;
    #pragma unroll
    for (int mt = 0; mt < 4; ++mt) {
        const int r0 = rowBase + wm + mt * 16 + g;
        const float xs0 = g_xsq[r0];
        const float xs1 = g_xsq[r0 + 8];
        float* p0 = C + (size_t)r0 * ND + colBase + wn;
        float* p1 = p0 + (size_t)8 * ND;
        #pragma unroll
        for (int nf = 0; nf < 4; ++nf) {
            const int col = nf * 8 + tg;
            const float w0 = g_wsq[colBase + wn + col];
            const float w1 = g_wsq[colBase + wn + col + 1];
            float2 v0, v1;
            v0.x = xs0 + w0 - 2.f * acc[mt][nf][0];
            v0.y = xs0 + w1 - 2.f * acc[mt][nf][1];
            v1.x = xs1 + w0 - 2.f * acc[mt][nf][2];
            v1.y = xs1 + w1 - 2.f * acc[mt][nf][3];
            *reinterpret_cast<float2*>(p0 + col) = v0;
            *reinterpret_cast<float2*>(p1 + col) = v1;
        }
    }
}

// ---------------------------------------------------------------------------
extern "C" void kernel_launch(void* const* d_in, const int* in_sizes, int n_in,
                              void* d_out, int out_size) {
    const float* x = (const float*)d_in[0];
    const float* w = (const float*)d_in[1];
    float* out = (float*)d_out;

    convert_x_kernel<<<MB / 8, 256>>>(x);
    convert_w_fused<<<ND / 32, 256>>>(w);

    cudaFuncSetAttribute(rbf_mma_gemm,
                         cudaFuncAttributeMaxDynamicSharedMemorySize, SMEM_BYTES);
    rbf_mma_gemm<<<dim3(ND / 128, MB / 128), 256, SMEM_BYTES>>>(out);
}